// round 13
// baseline (speedup 1.0000x reference)
#include <cuda_runtime.h>
#include <math.h>

#define Hh 64
#define Ww 64
#define MAXB 8
#define MAXP 512
#define MAXF 512
#define EPSd 1e-10f
#define KEXP 142.85714285714286f      // MULT*MULT/DELTA
#define EXPANDc 0.02f
#define NPIX (Hh * Ww)
#define QSCALE 33554432.0f            // 2^25
#define QINV   (1.0f/33554432.0f)
#define QCLAMP 32768.0f
#define COVQ   (1ULL << 40)
#define LB2THRESH 0.14f               // exp(-0.14*KEXP) < 2e-9

// scratch (device globals; zero-initialized at load, reset by resolve each run)
__device__ unsigned long long g_zpack[MAXB * NPIX];   // (ordered_z << 32) | (~fid)
__device__ unsigned long long g_lsum[MAXB * NPIX];    // quantized -log(factor) sum

__device__ __forceinline__ unsigned ford(float f) {
    unsigned u = __float_as_uint(f);
    return (u & 0x80000000u) ? ~u : (u | 0x80000000u);
}

// ---------------- Kernel 1: face-parallel splat ----------------
// 2 faces per 128-thread CTA; 64 threads (2 warps) per face.
__global__ void __launch_bounds__(128)
splat_kernel(const float* __restrict__ verts,
             const int* __restrict__ faces,
             const float* __restrict__ rot,
             const float* __restrict__ pos,
             const float* __restrict__ proj,
             float* __restrict__ out_normal1,
             int B, int P, int F)
{
    int gf  = blockIdx.x * 2 + (threadIdx.x >> 6);   // global face id in [0, B*F)
    int sub = threadIdx.x & 63;
    int b = gf / F;
    int fg = gf - b * F;

    float R0 = rot[b*9+0], R1 = rot[b*9+1], R2 = rot[b*9+2];
    float R3 = rot[b*9+3], R4 = rot[b*9+4], R5 = rot[b*9+5];
    float R6 = rot[b*9+6], R7 = rot[b*9+7], R8 = rot[b*9+8];
    float p0 = pos[b*3+0], p1 = pos[b*3+1], p2 = pos[b*3+2];
    float pr0 = proj[0], pr1 = proj[1], pr2 = proj[2];

    const int* fi = faces + (size_t)gf * 3;
    int i0 = fi[0], i1 = fi[1], i2 = fi[2];
    int idxs[3] = {i0, i1, i2};
    float pcx[3], pcy[3], pcz[3], X[3], Y[3];
    #pragma unroll
    for (int k = 0; k < 3; ++k) {
        const float* v = verts + ((size_t)(b * P + idxs[k])) * 3;
        float d0 = v[0]-p0, d1 = v[1]-p1, d2 = v[2]-p2;
        pcx[k] = R0*d0 + R1*d1 + R2*d2;
        pcy[k] = R3*d0 + R4*d1 + R5*d2;
        pcz[k] = R6*d0 + R7*d1 + R8*d2;
        float zz = pcz[k] * pr2;
        X[k] = (pcx[k] * pr0) / zz;
        Y[k] = (pcy[k] * pr1) / zz;
    }
    float e1x = pcx[1]-pcx[0], e1y = pcy[1]-pcy[0], e1z = pcz[1]-pcz[0];
    float e2x = pcx[2]-pcx[0], e2y = pcy[2]-pcy[0], e2z = pcz[2]-pcz[0];
    float nx = e1y*e2z - e1z*e2y;
    float ny = e1z*e2x - e1x*e2z;
    float nz = e1x*e2y - e1y*e2x;
    if (sub == 0) {
        float nrm = sqrtf(nx*nx + ny*ny + nz*nz) + 1e-12f;
        float* on = out_normal1 + (size_t)gf * 3;
        on[0] = nx / nrm; on[1] = ny / nrm; on[2] = nz / nrm;
    }

    float ax = X[0], ay = Y[0], bx = X[1], by = Y[1], cx = X[2], cy = Y[2];
    float z0 = pcz[0], z1 = pcz[1], z2s = pcz[2];

    float det = (by - cy)*(ax - cx) + (cx - bx)*(ay - cy);
    float adet = fabsf(det);
    float det_safe = (adet < EPSd) ? EPSd : det;
    float inv = 1.0f / det_safe;
    bool valid = (nz > 0.0f) && (adet > EPSd);

    float a0 = (by - cy) * inv, b0 = (cx - bx) * inv;
    float c0 = -(a0 * cx + b0 * cy);
    float a1 = (cy - ay) * inv, b1 = (ax - cx) * inv;
    float c1 = -(a1 * cx + b1 * cy);
    float dz0 = z0 - z2s, dz1 = z1 - z2s;

    float xmin = fminf(fminf(ax, bx), cx) - EXPANDc;
    float xmax = fmaxf(fmaxf(ax, bx), cx) + EXPANDc;
    float ymin = fminf(fminf(ay, by), cy) - EXPANDc;
    float ymax = fmaxf(fmaxf(ay, by), cy) + EXPANDc;

    // conservative integer pixel bbox (per-pixel float re-test keeps exactness)
    int x0 = max(0,    (int)floorf((xmin * (float)Ww + (float)Ww - 1.0f) * 0.5f));
    int x1 = min(Ww-1, (int)ceilf ((xmax * (float)Ww + (float)Ww - 1.0f) * 0.5f));
    int y0 = max(0,    (int)floorf(((float)(Hh-1) - ymax * (float)Hh) * 0.5f));
    int y1 = min(Hh-1, (int)ceilf (((float)(Hh-1) - ymin * (float)Hh) * 0.5f));
    if (x0 > x1 || y0 > y1) return;

    // segments (a->b),(b->c),(c->a)
    float v0x = bx - ax, v0y = by - ay;
    float inv0 = 1.0f / (v0x*v0x + v0y*v0y + 1e-12f);
    float v1x = cx - bx, v1y = cy - by;
    float inv1 = 1.0f / (v1x*v1x + v1y*v1y + 1e-12f);
    float v2x = ax - cx, v2y = ay - cy;
    float inv2 = 1.0f / (v2x*v2x + v2y*v2y + 1e-12f);
    // certified lower-bound scales: d2 >= min_j (w_j*det_safe)^2 * inv_edge_j
    float ds2 = det_safe * det_safe;
    float k20 = ds2 * inv1;   // w0 <-> edge (b,c)
    float k21 = ds2 * inv2;   // w1 <-> edge (c,a)
    float k22 = ds2 * inv0;   // w2 <-> edge (a,b)

    unsigned fidlow = 0xFFFFFFFFu - (unsigned)fg;
    int lane = sub & 31, wrow = sub >> 5;

    for (int yy = y0 + wrow; yy <= y1; yy += 2) {
        float py = ((float)Hh - 2.0f * (float)yy - 1.0f) / (float)Hh;
        bool yok = (py >= ymin) && (py <= ymax);
        for (int xx = x0 + lane; xx <= x1; xx += 32) {
            float px = (2.0f * (float)xx + 1.0f - (float)Ww) / (float)Ww;
            if (!yok || px < xmin || px > xmax) continue;

            float w0 = fmaf(a0, px, fmaf(b0, py, c0));
            float w1 = fmaf(a1, px, fmaf(b1, py, c1));
            float w2 = 1.0f - w0 - w1;
            int idx = (b * Hh + yy) * Ww + xx;

            if ((w0 >= 0.0f) && (w1 >= 0.0f) && (w2 >= 0.0f)) {
                atomicAdd(&g_lsum[idx], COVQ);          // factor = 0
                if (valid) {
                    float z = fmaf(w0, dz0, fmaf(w1, dz1, z2s));
                    unsigned long long pk = ((unsigned long long)ford(z) << 32) | fidlow;
                    atomicMax(&g_zpack[idx], pk);
                }
            } else {
                float lb2 = fminf(fminf(w0*w0*k20, w1*w1*k21), w2*w2*k22);
                if (lb2 <= LB2THRESH) {
                    float rx = px - ax, ry = py - ay;
                    float t0 = fminf(fmaxf((rx * v0x + ry * v0y) * inv0, 0.0f), 1.0f);
                    float ex = fmaf(-t0, v0x, rx), ey = fmaf(-t0, v0y, ry);
                    float d2 = ex * ex + ey * ey;

                    rx = px - bx; ry = py - by;
                    float t1 = fminf(fmaxf((rx * v1x + ry * v1y) * inv1, 0.0f), 1.0f);
                    ex = fmaf(-t1, v1x, rx); ey = fmaf(-t1, v1y, ry);
                    d2 = fminf(d2, ex * ex + ey * ey);

                    rx = px - cx; ry = py - cy;
                    float t2 = fminf(fmaxf((rx * v2x + ry * v2y) * inv2, 0.0f), 1.0f);
                    ex = fmaf(-t2, v2x, rx); ey = fmaf(-t2, v2y, ry);
                    d2 = fminf(d2, ex * ex + ey * ey);

                    float factor = 1.0f - __expf(-d2 * KEXP);
                    float nl = -__logf(factor);             // >= 0 (inf if factor==0)
                    nl = fminf(nl, QCLAMP);
                    unsigned long long q = (unsigned long long)(nl * QSCALE);
                    if (q) atomicAdd(&g_lsum[idx], q);
                }
            }
        }
    }
}

// ---------------- Kernel 2: per-pixel resolve (+ scratch reset) ----------------
__global__ void __launch_bounds__(256)
resolve_kernel(const float* __restrict__ verts,
               const int* __restrict__ faces,
               const float* __restrict__ rot,
               const float* __restrict__ pos,
               const float* __restrict__ proj,
               const float* __restrict__ colors,
               float* __restrict__ out,
               int B, int P, int F,
               int offP, int offH)
{
    int idx = blockIdx.x * blockDim.x + threadIdx.x;
    if (idx >= B * NPIX) return;
    int b = idx / NPIX;
    int pix = idx - b * NPIX;

    unsigned long long zp = g_zpack[idx];
    unsigned long long ls = g_lsum[idx];
    g_zpack[idx] = 0ULL;                 // reset for next replay
    g_lsum[idx]  = 0ULL;

    float improb = 1.0f - __expf(-(float)ls * QINV);

    float r = 0.0f, g = 0.0f, bl = 0.0f, hm = 0.0f;
    if (zp) {
        int fg = (int)(0xFFFFFFFFu - (unsigned)(zp & 0xFFFFFFFFull));

        float R0 = rot[b*9+0], R1 = rot[b*9+1], R2 = rot[b*9+2];
        float R3 = rot[b*9+3], R4 = rot[b*9+4], R5 = rot[b*9+5];
        float R6 = rot[b*9+6], R7 = rot[b*9+7], R8 = rot[b*9+8];
        float p0 = pos[b*3+0], p1 = pos[b*3+1], p2 = pos[b*3+2];
        float pr0 = proj[0], pr1 = proj[1], pr2 = proj[2];

        const int* fi = faces + ((size_t)(b * F + fg)) * 3;
        int i0 = fi[0], i1 = fi[1], i2 = fi[2];
        int idxs[3] = {i0, i1, i2};
        float X[3], Y[3];
        #pragma unroll
        for (int k = 0; k < 3; ++k) {
            const float* v = verts + ((size_t)(b * P + idxs[k])) * 3;
            float d0 = v[0]-p0, d1 = v[1]-p1, d2 = v[2]-p2;
            float px_ = R0*d0 + R1*d1 + R2*d2;
            float py_ = R3*d0 + R4*d1 + R5*d2;
            float pz_ = R6*d0 + R7*d1 + R8*d2;
            float zz = pz_ * pr2;
            X[k] = (px_ * pr0) / zz;
            Y[k] = (py_ * pr1) / zz;
        }
        float ax = X[0], ay = Y[0], bx = X[1], by = Y[1], cx = X[2], cy = Y[2];

        float det = (by - cy)*(ax - cx) + (cx - bx)*(ay - cy);
        float adet = fabsf(det);
        float det_safe = (adet < EPSd) ? EPSd : det;
        float inv = 1.0f / det_safe;

        float a0 = (by - cy) * inv, b0 = (cx - bx) * inv;
        float c0 = -(a0 * cx + b0 * cy);
        float a1 = (cy - ay) * inv, b1 = (ax - cx) * inv;
        float c1 = -(a1 * cx + b1 * cy);

        int y = pix >> 6, x = pix & 63;
        float px = (2.0f * (float)x + 1.0f - (float)Ww) / (float)Ww;
        float py = ((float)Hh - 2.0f * (float)y - 1.0f) / (float)Hh;
        float w0 = fmaf(a0, px, fmaf(b0, py, c0));
        float w1 = fmaf(a1, px, fmaf(b1, py, c1));
        float w2 = 1.0f - w0 - w1;

        const float* cA = colors + ((size_t)(b * P + i0)) * 3;
        const float* cB = colors + ((size_t)(b * P + i1)) * 3;
        const float* cC = colors + ((size_t)(b * P + i2)) * 3;
        r  = w0 * cA[0] + w1 * cB[0] + w2 * cC[0];
        g  = w0 * cA[1] + w1 * cB[1] + w2 * cC[1];
        bl = w0 * cA[2] + w1 * cB[2] + w2 * cC[2];
        hm = w0 + w1 + w2;
    }

    float* rgb = out + (size_t)idx * 3;
    rgb[0] = r; rgb[1] = g; rgb[2] = bl;
    out[offP + idx] = improb;
    out[offH + idx] = hm;
}

extern "C" void kernel_launch(void* const* d_in, const int* in_sizes, int n_in,
                              void* d_out, int out_size)
{
    const float* verts  = (const float*)d_in[0];
    const int*   faces  = (const int*)d_in[1];
    const float* rot    = (const float*)d_in[2];
    const float* pos    = (const float*)d_in[3];
    const float* proj   = (const float*)d_in[4];
    const float* colors = (const float*)d_in[5];
    float* out = (float*)d_out;

    int B = in_sizes[3] / 3;
    int P = in_sizes[0] / (3 * B);
    int F = in_sizes[1] / (3 * B);

    int offP = B * NPIX * 3;        // improb
    int offN = offP + B * NPIX;     // normal1
    int offH = offN + B * F * 3;    // hardmask

    int nfaces = B * F;
    splat_kernel<<<nfaces / 2, 128>>>(verts, faces, rot, pos, proj,
                                      out + offN, B, P, F);

    int npx = B * NPIX;
    resolve_kernel<<<(npx + 255) / 256, 256>>>(verts, faces, rot, pos, proj,
                                               colors, out, B, P, F, offP, offH);
}

// round 14
// speedup vs baseline: 1.4797x; 1.4797x over previous
#include <cuda_runtime.h>
#include <math.h>

#define Hh 64
#define Ww 64
#define MAXB 8
#define MAXP 512
#define MAXF 512
#define RECF 32
#define NCHUNK 16
#define FPCmax 32
#define NTILE 32
#define EPSd 1e-10f
#define KEXP 142.85714285714286f   // MULT*MULT/DELTA
#define EXPANDc 0.02f
#define NPIX (Hh * Ww)
#define LB2THRESH 0.14f            // exp(-0.14*KEXP) < 2e-9 -> factor ~ 1

// scratch (device globals; no allocation allowed)
__device__ float4 g_partA[MAXB * NCHUNK * NPIX];   // bestz, bw0, bw1, bestfid(as float)
__device__ float  g_partP[MAXB * NCHUNK * NPIX];   // prod
__device__ int    g_cnt[MAXB * NTILE];             // per (b,tile) arrival counter

__global__ void __launch_bounds__(128, 12)
render_kernel(const float* __restrict__ verts,
              const int* __restrict__ faces,
              const float* __restrict__ rot,
              const float* __restrict__ pos,
              const float* __restrict__ proj,
              const float* __restrict__ colors,
              float* __restrict__ out,
              int B, int P, int F,
              int offP, int offN, int offH)
{
    __shared__ float sface[FPCmax * RECF];   // 4 KB
    __shared__ int wcnt0;
    __shared__ int sh_old;

    int b = blockIdx.z, chunk = blockIdx.y, tile = blockIdx.x;
    int FPC = F / NCHUNK;                    // 32
    int tid = threadIdx.x;
    int lane = tid & 31, wid = tid >> 5;
    int tx = tile & 3, ty = tile >> 2;       // 4 x-tiles (16px), 8 y-tiles (8px)

    // NDC extents of this 16x8 pixel tile
    float txlo = (2.0f * (float)(tx*16)      + 1.0f - (float)Ww) / (float)Ww;
    float txhi = (2.0f * (float)(tx*16 + 15) + 1.0f - (float)Ww) / (float)Ww;
    float tyhi = ((float)Hh - 2.0f * (float)(ty*8)      - 1.0f) / (float)Hh;
    float tylo = ((float)Hh - 2.0f * (float)(ty*8 + 7)  - 1.0f) / (float)Hh;

    // ---- per-face geometry (threads 0..FPC-1, warp 0) ----
    bool acc = false;
    int fg = 0;
    float ax=0, ay=0, bx=0, by=0, cx=0, cy=0;
    float z0=0, z1=0, z2s=0, nz=0;
    float xmin=0, xmax=0, ymin=0, ymax=0;

    if (tid < FPC) {
        float R0 = rot[b*9+0], R1 = rot[b*9+1], R2 = rot[b*9+2];
        float R3 = rot[b*9+3], R4 = rot[b*9+4], R5 = rot[b*9+5];
        float R6 = rot[b*9+6], R7 = rot[b*9+7], R8 = rot[b*9+8];
        float p0 = pos[b*3+0], p1 = pos[b*3+1], p2 = pos[b*3+2];
        float pr0 = proj[0], pr1 = proj[1], pr2 = proj[2];

        fg = chunk * FPC + tid;
        const int* fi = faces + ((size_t)(b * F + fg)) * 3;
        int idxs[3] = {fi[0], fi[1], fi[2]};
        float pcx[3], pcy[3], pcz[3], X[3], Y[3];
        #pragma unroll
        for (int k = 0; k < 3; ++k) {
            const float* v = verts + ((size_t)(b * P + idxs[k])) * 3;
            float d0 = v[0]-p0, d1 = v[1]-p1, d2 = v[2]-p2;
            pcx[k] = R0*d0 + R1*d1 + R2*d2;
            pcy[k] = R3*d0 + R4*d1 + R5*d2;
            pcz[k] = R6*d0 + R7*d1 + R8*d2;
            float zz = pcz[k] * pr2;
            X[k] = (pcx[k] * pr0) / zz;
            Y[k] = (pcy[k] * pr1) / zz;
        }
        float e1x = pcx[1]-pcx[0], e1y = pcy[1]-pcy[0], e1z = pcz[1]-pcz[0];
        float e2x = pcx[2]-pcx[0], e2y = pcy[2]-pcy[0], e2z = pcz[2]-pcz[0];
        float nx = e1y*e2z - e1z*e2y;
        float ny = e1z*e2x - e1x*e2z;
        nz = e1x*e2y - e1y*e2x;
        if (tile == 0) {
            float nrm = sqrtf(nx*nx + ny*ny + nz*nz) + 1e-12f;
            float* on = out + offN + ((size_t)(b * F + fg)) * 3;
            on[0] = nx / nrm; on[1] = ny / nrm; on[2] = nz / nrm;
        }
        ax = X[0]; ay = Y[0]; bx = X[1]; by = Y[1]; cx = X[2]; cy = Y[2];
        z0 = pcz[0]; z1 = pcz[1]; z2s = pcz[2];

        xmin = fminf(fminf(ax, bx), cx) - EXPANDc;
        xmax = fmaxf(fmaxf(ax, bx), cx) + EXPANDc;
        ymin = fminf(fminf(ay, by), cy) - EXPANDc;
        ymax = fmaxf(fmaxf(ay, by), cy) + EXPANDc;
        acc = (xmin <= txhi) && (xmax >= txlo) && (ymin <= tyhi) && (ymax >= tylo);
    }

    // ---- order-preserving compaction (faces live in warp 0) ----
    unsigned m = __ballot_sync(0xffffffffu, acc);
    if (tid == 0) wcnt0 = __popc(m);

    if (acc) {
        int slot = __popc(m & ((1u << lane) - 1u));
        float* Rr = sface + slot * RECF;

        float det = (by - cy)*(ax - cx) + (cx - bx)*(ay - cy);
        float adet = fabsf(det);
        float det_safe = (adet < EPSd) ? EPSd : det;
        float inv = 1.0f / det_safe;
        bool valid = (nz > 0.0f) && (adet > EPSd);

        float a0 = (by - cy) * inv, b0 = (cx - bx) * inv;
        float c0 = -(a0 * cx + b0 * cy);
        float a1 = (cy - ay) * inv, b1 = (ax - cx) * inv;
        float c1 = -(a1 * cx + b1 * cy);

        float v0x = bx - ax, v0y = by - ay;
        float inv0 = 1.0f / (v0x*v0x + v0y*v0y + 1e-12f);
        float v1x = cx - bx, v1y = cy - by;
        float inv1 = 1.0f / (v1x*v1x + v1y*v1y + 1e-12f);
        float v2x = ax - cx, v2y = ay - cy;
        float inv2 = 1.0f / (v2x*v2x + v2y*v2y + 1e-12f);
        float ds2 = det_safe * det_safe;

        Rr[0] = xmin; Rr[1] = xmax; Rr[2] = ymin; Rr[3] = ymax;
        Rr[4] = a0; Rr[5] = b0; Rr[6] = c0; Rr[7] = valid ? (z0 - z2s) : 0.0f;
        Rr[8] = a1; Rr[9] = b1; Rr[10] = c1; Rr[11] = valid ? (z1 - z2s) : 0.0f;
        Rr[12] = valid ? z2s : -1e10f;
        Rr[13] = valid ? (float)fg : -1.0f;
        Rr[14] = inv2;
        Rr[15] = 0.0f;
        Rr[16] = v0x; Rr[17] = v0y; Rr[18] = inv0; Rr[19] = inv1;
        Rr[20] = bx;  Rr[21] = by;  Rr[22] = v1x;  Rr[23] = v1y;
        Rr[24] = cx;  Rr[25] = cy;  Rr[26] = v2x;  Rr[27] = v2y;
        Rr[28] = ds2 * inv1;   // k2 for w0 (edge b-c)
        Rr[29] = ds2 * inv2;   // k2 for w1 (edge c-a)
        Rr[30] = ds2 * inv0;   // k2 for w2 (edge a-b)
        Rr[31] = 0.0f;
    }
    __syncthreads();
    int nf = wcnt0;

    // ---- pixel mapping: 16x8 tile, 4 warps of 8x4, 1 pixel/thread ----
    int lx = lane & 7, ly = lane >> 3;
    int wx = wid & 1, wy = wid >> 1;
    int x = tx * 16 + wx * 8 + lx;
    int y = ty * 8  + wy * 4 + ly;

    float px = (2.0f * (float)x + 1.0f - (float)Ww) / (float)Ww;
    float py = ((float)Hh - 2.0f * (float)y - 1.0f) / (float)Hh;

    float prod = 1.0f;
    float bestz = -1e30f;
    float bw0 = 0.0f, bw1 = 0.0f, bf = -1.0f;

    float4 bb = (nf > 0) ? *(const float4*)(&sface[0]) : make_float4(0,0,0,0);
    for (int f = 0; f < nf; ++f) {
        float4 bbn;
        if (f + 1 < nf) bbn = *(const float4*)(&sface[(f + 1) * RECF]);
        const float* Rr = &sface[f * RECF];
        bool inb = (px >= bb.x) && (px <= bb.y) && (py >= bb.z) && (py <= bb.w);
        if (__ballot_sync(0xffffffffu, inb) != 0u) {
            float4 e0 = *(const float4*)(Rr + 4);
            float4 e1 = *(const float4*)(Rr + 8);
            float4 zf = *(const float4*)(Rr + 12);   // zc, fid, inv2, -
            float4 k4 = *(const float4*)(Rr + 28);   // k2_w0, k2_w1, k2_w2, -

            float w0 = fmaf(e0.x, px, fmaf(e0.y, py, e0.z));
            float w1 = fmaf(e1.x, px, fmaf(e1.y, py, e1.z));
            float w2 = 1.0f - w0 - w1;
            bool covered = (w0 >= 0.0f) && (w1 >= 0.0f) && (w2 >= 0.0f);
            bool cov = inb && covered;

            // z/argmax block only if some lane is covered
            if (__any_sync(0xffffffffu, cov)) {
                float z = fmaf(w0, e0.w, fmaf(w1, e1.w, zf.x));
                bool upd = cov && (z > bestz);
                bestz = upd ? z : bestz;
                bw0 = upd ? w0 : bw0;
                bw1 = upd ? w1 : bw1;
                bf  = upd ? zf.y : bf;
                prod = cov ? 0.0f : prod;
            }

            // segment+exp block only if some lane is in the near band
            float lb2 = fminf(fminf(w0*w0*k4.x, w1*w1*k4.y), w2*w2*k4.z);
            bool need = inb && !covered && (lb2 <= LB2THRESH);
            if (__any_sync(0xffffffffu, need)) {
                float4 s0 = *(const float4*)(Rr + 16);  // v0x,v0y,inv0,inv1
                float4 s1 = *(const float4*)(Rr + 20);  // bx,by,v1x,v1y
                float4 s2 = *(const float4*)(Rr + 24);  // cx,cy,v2x,v2y
                float axr = s2.x + s2.z;                // a = c + v2
                float ayr = s2.y + s2.w;

                float rx = px - axr, ry = py - ayr;
                float t0 = __saturatef((rx * s0.x + ry * s0.y) * s0.z);
                float ex = fmaf(-t0, s0.x, rx), ey = fmaf(-t0, s0.y, ry);
                float d2 = ex * ex + ey * ey;

                rx = px - s1.x; ry = py - s1.y;
                float t1 = __saturatef((rx * s1.z + ry * s1.w) * s0.w);
                ex = fmaf(-t1, s1.z, rx); ey = fmaf(-t1, s1.w, ry);
                d2 = fminf(d2, ex * ex + ey * ey);

                rx = px - s2.x; ry = py - s2.y;
                float t2 = __saturatef((rx * s2.z + ry * s2.w) * zf.z);
                ex = fmaf(-t2, s2.z, rx); ey = fmaf(-t2, s2.w, ry);
                d2 = fminf(d2, ex * ex + ey * ey);

                float factor = 1.0f - __expf(-d2 * KEXP);
                prod *= (need ? factor : 1.0f);
            }
        }
        bb = bbn;
    }

    int pix = y * Ww + x;
    int o = (b * NCHUNK + chunk) * NPIX + pix;
    __stcg(&g_partA[o], make_float4(bestz, bw0, bw1, bf));
    __stcg(&g_partP[o], prod);

    // ---- last CTA per (b,tile) combines ----
    __threadfence();
    __syncthreads();
    if (tid == 0) sh_old = atomicAdd(&g_cnt[b * NTILE + tile], 1);
    __syncthreads();
    if (sh_old != NCHUNK - 1) return;
    __threadfence();

    float Z = -1e38f, b0c = 0.0f, b1c = 0.0f, bff = -1.0f;
    float pacc = 1.0f;
    #pragma unroll
    for (int c = 0; c < NCHUNK; ++c) {
        int oo = (b * NCHUNK + c) * NPIX + pix;
        float4 a = __ldcg(&g_partA[oo]);
        pacc *= __ldcg(&g_partP[oo]);
        bool u = (a.x > Z);
        Z = u ? a.x : Z; b0c = u ? a.y : b0c; b1c = u ? a.z : b1c; bff = u ? a.w : bff;
    }

    float r = 0.0f, g = 0.0f, bl = 0.0f, hm = 0.0f;
    if (bff >= 0.0f) {
        int fid = (int)bff;
        const int* fi = faces + ((size_t)(b * F + fid)) * 3;
        const float* cA = colors + ((size_t)(b * P + fi[0])) * 3;
        const float* cB = colors + ((size_t)(b * P + fi[1])) * 3;
        const float* cC = colors + ((size_t)(b * P + fi[2])) * 3;
        float w2 = 1.0f - b0c - b1c;
        r  = b0c * cA[0] + b1c * cB[0] + w2 * cC[0];
        g  = b0c * cA[1] + b1c * cB[1] + w2 * cC[1];
        bl = b0c * cA[2] + b1c * cB[2] + w2 * cC[2];
        hm = b0c + b1c + w2;
    }

    int gidx = b * NPIX + pix;
    float* rgb = out + (size_t)gidx * 3;
    rgb[0] = r; rgb[1] = g; rgb[2] = bl;
    out[offP + gidx] = 1.0f - pacc;
    out[offH + gidx] = hm;

    if (tid == 0) atomicExch(&g_cnt[b * NTILE + tile], 0);   // reset for next replay
}

extern "C" void kernel_launch(void* const* d_in, const int* in_sizes, int n_in,
                              void* d_out, int out_size)
{
    const float* verts  = (const float*)d_in[0];
    const int*   faces  = (const int*)d_in[1];
    const float* rot    = (const float*)d_in[2];
    const float* pos    = (const float*)d_in[3];
    const float* proj   = (const float*)d_in[4];
    const float* colors = (const float*)d_in[5];
    float* out = (float*)d_out;

    int B = in_sizes[3] / 3;
    int P = in_sizes[0] / (3 * B);
    int F = in_sizes[1] / (3 * B);

    int offP = B * NPIX * 3;        // improb
    int offN = offP + B * NPIX;     // normal1
    int offH = offN + B * F * 3;    // hardmask

    dim3 grid(NTILE, NCHUNK, B);
    render_kernel<<<grid, 128>>>(verts, faces, rot, pos, proj, colors, out,
                                 B, P, F, offP, offN, offH);
}

// round 15
// speedup vs baseline: 1.4813x; 1.0011x over previous
#include <cuda_runtime.h>
#include <math.h>

#define Hh 64
#define Ww 64
#define MAXB 8
#define MAXP 512
#define MAXF 512
#define RECF 32
#define NCHUNK 16
#define FPCmax 32
#define NTILE 16
#define EPSd 1e-10f
#define KEXP 142.85714285714286f   // MULT*MULT/DELTA
#define EXPANDc 0.02f
#define NPIX (Hh * Ww)
#define DPX 0.25f                  // px(x+8) - px(x) = 16/64

// scratch (device globals; no allocation allowed)
__device__ float4 g_partA[MAXB * NCHUNK * NPIX];   // bestz, bw0, bw1, bestfid(as float)
__device__ float  g_partP[MAXB * NCHUNK * NPIX];   // prod
__device__ int    g_cnt[MAXB * NTILE];             // per (b,tile) arrival counter

__global__ void __launch_bounds__(128, 9)
render_kernel(const float* __restrict__ verts,
              const int* __restrict__ faces,
              const float* __restrict__ rot,
              const float* __restrict__ pos,
              const float* __restrict__ proj,
              const float* __restrict__ colors,
              float* __restrict__ out,
              int B, int P, int F,
              int offP, int offN, int offH)
{
    __shared__ float sface[FPCmax * RECF];   // 4 KB
    __shared__ int wcnt0;
    __shared__ int sh_old;

    int b = blockIdx.z, chunk = blockIdx.y, tile = blockIdx.x;
    int FPC = F / NCHUNK;                    // 32
    int tid = threadIdx.x;
    int lane = tid & 31, wid = tid >> 5;
    int tx = tile & 3, ty = tile >> 2;       // 4x4 tiles of 16x16 px

    // NDC extents of this 16x16 pixel tile
    float txlo = (2.0f * (float)(tx*16)      + 1.0f - (float)Ww) / (float)Ww;
    float txhi = (2.0f * (float)(tx*16 + 15) + 1.0f - (float)Ww) / (float)Ww;
    float tyhi = ((float)Hh - 2.0f * (float)(ty*16)      - 1.0f) / (float)Hh;
    float tylo = ((float)Hh - 2.0f * (float)(ty*16 + 15) - 1.0f) / (float)Hh;

    // ---- per-face geometry (threads 0..FPC-1, warp 0) ----
    bool acc = false;
    int fg = 0;
    float ax=0, ay=0, bx=0, by=0, cx=0, cy=0;
    float z0=0, z1=0, z2s=0, nz=0;
    float xmin=0, xmax=0, ymin=0, ymax=0;

    if (tid < FPC) {
        float R0 = rot[b*9+0], R1 = rot[b*9+1], R2 = rot[b*9+2];
        float R3 = rot[b*9+3], R4 = rot[b*9+4], R5 = rot[b*9+5];
        float R6 = rot[b*9+6], R7 = rot[b*9+7], R8 = rot[b*9+8];
        float p0 = pos[b*3+0], p1 = pos[b*3+1], p2 = pos[b*3+2];
        float pr0 = proj[0], pr1 = proj[1], pr2 = proj[2];

        fg = chunk * FPC + tid;
        const int* fi = faces + ((size_t)(b * F + fg)) * 3;
        int idxs[3] = {fi[0], fi[1], fi[2]};
        float pcx[3], pcy[3], pcz[3], X[3], Y[3];
        #pragma unroll
        for (int k = 0; k < 3; ++k) {
            const float* v = verts + ((size_t)(b * P + idxs[k])) * 3;
            float d0 = v[0]-p0, d1 = v[1]-p1, d2 = v[2]-p2;
            pcx[k] = R0*d0 + R1*d1 + R2*d2;
            pcy[k] = R3*d0 + R4*d1 + R5*d2;
            pcz[k] = R6*d0 + R7*d1 + R8*d2;
            float zz = pcz[k] * pr2;
            X[k] = (pcx[k] * pr0) / zz;
            Y[k] = (pcy[k] * pr1) / zz;
        }
        float e1x = pcx[1]-pcx[0], e1y = pcy[1]-pcy[0], e1z = pcz[1]-pcz[0];
        float e2x = pcx[2]-pcx[0], e2y = pcy[2]-pcy[0], e2z = pcz[2]-pcz[0];
        float nx = e1y*e2z - e1z*e2y;
        float ny = e1z*e2x - e1x*e2z;
        nz = e1x*e2y - e1y*e2x;
        if (tile == 0) {
            float nrm = sqrtf(nx*nx + ny*ny + nz*nz) + 1e-12f;
            float* on = out + offN + ((size_t)(b * F + fg)) * 3;
            on[0] = nx / nrm; on[1] = ny / nrm; on[2] = nz / nrm;
        }
        ax = X[0]; ay = Y[0]; bx = X[1]; by = Y[1]; cx = X[2]; cy = Y[2];
        z0 = pcz[0]; z1 = pcz[1]; z2s = pcz[2];

        xmin = fminf(fminf(ax, bx), cx) - EXPANDc;
        xmax = fmaxf(fmaxf(ax, bx), cx) + EXPANDc;
        ymin = fminf(fminf(ay, by), cy) - EXPANDc;
        ymax = fmaxf(fmaxf(ay, by), cy) + EXPANDc;
        acc = (xmin <= txhi) && (xmax >= txlo) && (ymin <= tyhi) && (ymax >= tylo);
    }

    // ---- order-preserving compaction (faces live in warp 0) ----
    unsigned m = __ballot_sync(0xffffffffu, acc);
    if (tid == 0) wcnt0 = __popc(m);

    if (acc) {
        int slot = __popc(m & ((1u << lane) - 1u));
        float* Rr = sface + slot * RECF;

        float det = (by - cy)*(ax - cx) + (cx - bx)*(ay - cy);
        float adet = fabsf(det);
        float det_safe = (adet < EPSd) ? EPSd : det;
        float inv = 1.0f / det_safe;
        bool valid = (nz > 0.0f) && (adet > EPSd);

        float a0 = (by - cy) * inv, b0 = (cx - bx) * inv;
        float c0 = -(a0 * cx + b0 * cy);
        float a1 = (cy - ay) * inv, b1 = (ax - cx) * inv;
        float c1 = -(a1 * cx + b1 * cy);

        Rr[0] = xmin; Rr[1] = xmax; Rr[2] = ymin; Rr[3] = ymax;
        Rr[4] = a0; Rr[5] = b0; Rr[6] = c0; Rr[7] = valid ? (z0 - z2s) : 0.0f;
        Rr[8] = a1; Rr[9] = b1; Rr[10] = c1; Rr[11] = valid ? (z1 - z2s) : 0.0f;
        Rr[12] = valid ? z2s : -1e10f;
        Rr[13] = valid ? (float)fg : -1.0f;
        Rr[14] = ax; Rr[15] = ay;
        float v0x = bx - ax, v0y = by - ay;
        Rr[16] = v0x; Rr[17] = v0y;
        Rr[18] = 1.0f / (v0x*v0x + v0y*v0y + 1e-12f);
        Rr[19] = bx;
        Rr[20] = by;
        float v1x = cx - bx, v1y = cy - by;
        Rr[21] = v1x; Rr[22] = v1y;
        Rr[23] = 1.0f / (v1x*v1x + v1y*v1y + 1e-12f);
        Rr[24] = cx; Rr[25] = cy;
        float v2x = ax - cx, v2y = ay - cy;
        Rr[26] = v2x; Rr[27] = v2y;
        Rr[28] = 1.0f / (v2x*v2x + v2y*v2y + 1e-12f);
    }
    __syncthreads();
    int nf = wcnt0;

    // ---- pixel mapping: 16x16 tile, warp = 16x4 strip, 2 px/thread (x, x+8) ----
    int lx = lane & 7, ly = lane >> 3;       // 8x4 base
    int x  = tx * 16 + lx;                   // pixel A; pixel B = x + 8
    int y  = ty * 16 + wid * 4 + ly;

    float px  = (2.0f * (float)x + 1.0f - (float)Ww) / (float)Ww;
    float pxB = px + DPX;
    float py  = ((float)Hh - 2.0f * (float)y - 1.0f) / (float)Hh;

    float prodA = 1.0f, prodB = 1.0f;
    float zA = -1e30f, zB = -1e30f;
    float w0A = 0, w1A = 0, fA = -1.0f;
    float w0B = 0, w1B = 0, fB = -1.0f;

    float4 bb = (nf > 0) ? *(const float4*)(&sface[0]) : make_float4(0,0,0,0);
    for (int f = 0; f < nf; ++f) {
        float4 bbn;
        if (f + 1 < nf) bbn = *(const float4*)(&sface[(f + 1) * RECF]);
        const float* Rr = &sface[f * RECF];
        bool yok = (py >= bb.z) && (py <= bb.w);
        bool inbA = yok && (px  >= bb.x) && (px  <= bb.y);
        bool inbB = yok && (pxB >= bb.x) && (pxB <= bb.y);
        if (__ballot_sync(0xffffffffu, inbA || inbB) != 0u) {
            float4 e0 = *(const float4*)(Rr + 4);
            float4 e1 = *(const float4*)(Rr + 8);
            float4 zf = *(const float4*)(Rr + 12);   // zc, fid, ax, ay

            float w0a = fmaf(e0.x, px, fmaf(e0.y, py, e0.z));
            float w1a = fmaf(e1.x, px, fmaf(e1.y, py, e1.z));
            float w0b = fmaf(e0.x, DPX, w0a);
            float w1b = fmaf(e1.x, DPX, w1a);
            float w2a = 1.0f - w0a - w1a;
            float w2b = 1.0f - w0b - w1b;
            bool covA = inbA && (w0a >= 0.0f) && (w1a >= 0.0f) && (w2a >= 0.0f);
            bool covB = inbB && (w0b >= 0.0f) && (w1b >= 0.0f) && (w2b >= 0.0f);

            if (__any_sync(0xffffffffu, covA || covB)) {
                float za = fmaf(w0a, e0.w, fmaf(w1a, e1.w, zf.x));
                float zb = fmaf(w0b, e0.w, fmaf(w1b, e1.w, zf.x));
                bool uA = covA && (za > zA);
                zA = uA ? za : zA; w0A = uA ? w0a : w0A; w1A = uA ? w1a : w1A; fA = uA ? zf.y : fA;
                bool uB = covB && (zb > zB);
                zB = uB ? zb : zB; w0B = uB ? w0b : w0B; w1B = uB ? w1b : w1B; fB = uB ? zf.y : fB;
                prodA = covA ? 0.0f : prodA;
                prodB = covB ? 0.0f : prodB;
            }

            bool needA = inbA && !covA;
            bool needB = inbB && !covB;
            if (__any_sync(0xffffffffu, needA || needB)) {
                float4 s0 = *(const float4*)(Rr + 16);   // v0x,v0y,inv0,bx
                float4 s1 = *(const float4*)(Rr + 20);   // by,v1x,v1y,inv1
                float4 s2 = *(const float4*)(Rr + 24);   // cx,cy,v2x,v2y
                float inv2 = Rr[28];

                // segment 0 (a->b)
                float rx = px - zf.z, ry = py - zf.w;
                float dot = rx * s0.x + ry * s0.y;
                float t  = __saturatef(dot * s0.z);
                float ex = fmaf(-t, s0.x, rx), ey = fmaf(-t, s0.y, ry);
                float d2a = ex * ex + ey * ey;
                float rxB = rx + DPX;
                float dotB = fmaf(DPX, s0.x, dot);
                float tB = __saturatef(dotB * s0.z);
                ex = fmaf(-tB, s0.x, rxB); ey = fmaf(-tB, s0.y, ry);
                float d2b = ex * ex + ey * ey;

                // segment 1 (b->c)
                rx = px - s0.w; ry = py - s1.x;
                dot = rx * s1.y + ry * s1.z;
                t = __saturatef(dot * s1.w);
                ex = fmaf(-t, s1.y, rx); ey = fmaf(-t, s1.z, ry);
                d2a = fminf(d2a, ex * ex + ey * ey);
                rxB = rx + DPX;
                dotB = fmaf(DPX, s1.y, dot);
                tB = __saturatef(dotB * s1.w);
                ex = fmaf(-tB, s1.y, rxB); ey = fmaf(-tB, s1.z, ry);
                d2b = fminf(d2b, ex * ex + ey * ey);

                // segment 2 (c->a)
                rx = px - s2.x; ry = py - s2.y;
                dot = rx * s2.z + ry * s2.w;
                t = __saturatef(dot * inv2);
                ex = fmaf(-t, s2.z, rx); ey = fmaf(-t, s2.w, ry);
                d2a = fminf(d2a, ex * ex + ey * ey);
                rxB = rx + DPX;
                dotB = fmaf(DPX, s2.z, dot);
                tB = __saturatef(dotB * inv2);
                ex = fmaf(-tB, s2.z, rxB); ey = fmaf(-tB, s2.w, ry);
                d2b = fminf(d2b, ex * ex + ey * ey);

                float fa = 1.0f - __expf(-d2a * KEXP);
                float fb = 1.0f - __expf(-d2b * KEXP);
                prodA *= (needA ? fa : 1.0f);
                prodB *= (needB ? fb : 1.0f);
            }
        }
        bb = bbn;
    }

    int pixA = y * Ww + x;
    int pixB = pixA + 8;
    int oA = (b * NCHUNK + chunk) * NPIX + pixA;
    __stcg(&g_partA[oA], make_float4(zA, w0A, w1A, fA));
    __stcg(&g_partP[oA], prodA);
    int oB = oA + 8;
    __stcg(&g_partA[oB], make_float4(zB, w0B, w1B, fB));
    __stcg(&g_partP[oB], prodB);

    // ---- last CTA per (b,tile) combines ----
    __threadfence();
    __syncthreads();
    if (tid == 0) sh_old = atomicAdd(&g_cnt[b * NTILE + tile], 1);
    __syncthreads();
    if (sh_old != NCHUNK - 1) return;
    __threadfence();

    #pragma unroll
    for (int pp = 0; pp < 2; ++pp) {
        int pix = (pp == 0) ? pixA : pixB;
        float Z = -1e38f, b0c = 0.0f, b1c = 0.0f, bff = -1.0f;
        float pacc = 1.0f;
        #pragma unroll
        for (int c = 0; c < NCHUNK; ++c) {
            int oo = (b * NCHUNK + c) * NPIX + pix;
            float4 a = __ldcg(&g_partA[oo]);
            pacc *= __ldcg(&g_partP[oo]);
            bool u = (a.x > Z);
            Z = u ? a.x : Z; b0c = u ? a.y : b0c; b1c = u ? a.z : b1c; bff = u ? a.w : bff;
        }

        float r = 0.0f, g = 0.0f, bl = 0.0f, hm = 0.0f;
        if (bff >= 0.0f) {
            int fid = (int)bff;
            const int* fi = faces + ((size_t)(b * F + fid)) * 3;
            const float* cA = colors + ((size_t)(b * P + fi[0])) * 3;
            const float* cB = colors + ((size_t)(b * P + fi[1])) * 3;
            const float* cC = colors + ((size_t)(b * P + fi[2])) * 3;
            float w2 = 1.0f - b0c - b1c;
            r  = b0c * cA[0] + b1c * cB[0] + w2 * cC[0];
            g  = b0c * cA[1] + b1c * cB[1] + w2 * cC[1];
            bl = b0c * cA[2] + b1c * cB[2] + w2 * cC[2];
            hm = b0c + b1c + w2;
        }

        int gidx = b * NPIX + pix;
        float* rgb = out + (size_t)gidx * 3;
        rgb[0] = r; rgb[1] = g; rgb[2] = bl;
        out[offP + gidx] = 1.0f - pacc;
        out[offH + gidx] = hm;
    }

    if (tid == 0) atomicExch(&g_cnt[b * NTILE + tile], 0);   // reset for next replay
}

extern "C" void kernel_launch(void* const* d_in, const int* in_sizes, int n_in,
                              void* d_out, int out_size)
{
    const float* verts  = (const float*)d_in[0];
    const int*   faces  = (const int*)d_in[1];
    const float* rot    = (const float*)d_in[2];
    const float* pos    = (const float*)d_in[3];
    const float* proj   = (const float*)d_in[4];
    const float* colors = (const float*)d_in[5];
    float* out = (float*)d_out;

    int B = in_sizes[3] / 3;
    int P = in_sizes[0] / (3 * B);
    int F = in_sizes[1] / (3 * B);

    int offP = B * NPIX * 3;        // improb
    int offN = offP + B * NPIX;     // normal1
    int offH = offN + B * F * 3;    // hardmask

    dim3 grid(NTILE, NCHUNK, B);
    render_kernel<<<grid, 128>>>(verts, faces, rot, pos, proj, colors, out,
                                 B, P, F, offP, offN, offH);
}